// round 13
// baseline (speedup 1.0000x reference)
#include <cuda_runtime.h>
#include <cuda_bf16.h>
#include <cstdint>
#include <cstddef>

#define NE   32
#define NK   4
#define NH   2048
#define NI   2048
#define NT   512
#define NCAP 256
#define N1   4096   // 2*I
#define NKC  64     // K / BK, BK = 32

// dynamic smem layout (bytes): BM=128, BN=128, BK=32, 3-stage raw + double packed
#define SM_A_STRIDE 6144      // 128 rows * 48B (padded, conflict-free frag reads)
#define SM_B_OFF    18432     // 3 * SM_A_STRIDE
#define SM_B_STRIDE 16384     // worst-case raw stage: 32k x 128n x 4B
#define SM_P_OFF    67584     // SM_B_OFF + 3 * SM_B_STRIDE
#define SM_P_HALF   1088      // 8 * 136 ints
#define SM_TOTAL    76288     // SM_P_OFF + 2 * 4352

// ---------------- scratch ----------------
__device__ int8_t g_qx[NT * NH];
__device__ float  g_xscale[NT];
__device__ int    g_topk_ids[NT * NK];
__device__ float  g_topk_w[NT * NK];
__device__ int    g_pos[NT * NK];
__device__ int    g_count[NE];
__device__ int    g_row_tok[NE * NCAP];
__device__ int    g_row_flat[NE * NCAP];
__device__ float  g_act[(size_t)NE * NCAP * NI];
__device__ int8_t g_q2[(size_t)NE * NCAP * NI];
__device__ float  g_s2[NE * NCAP];
__device__ float  g_dn[(size_t)NT * NK * NH];

__device__ int    g_mode;      // 0=int8 packed, 1=int32, 2=f32, 3=bf16
__device__ int    g_gu_swap;
__device__ int    g_dn_swap;

// ---------------- 0. detect dtype + classify scale/bias ----------------
__global__ void prep_kernel(const void* __restrict__ w,
                            const float* __restrict__ gua, const float* __restrict__ dna) {
    if (blockIdx.x == 0) {
        __shared__ int votes[4];
        if (threadIdx.x < 4) votes[threadIdx.x] = 0;
        __syncthreads();
        const int* wi = (const int*)w;
        int v8 = 0, v32 = 0, vf = 0, vb = 0;
        for (int i = threadIdx.x; i < 8192; i += 256) {
            int v = wi[i];
            if (v == 0) continue;
            if (v >= -127 && v <= 127) { v32++; continue; }
            float f = __int_as_float(v);
            if (fabsf(f) <= 127.f && f == rintf(f)) { vf++; continue; }
            float b0 = __uint_as_float(((unsigned)v & 0xFFFFu) << 16);
            float b1 = __uint_as_float(((unsigned)v) & 0xFFFF0000u);
            if (fabsf(b0) <= 127.f && b0 == rintf(b0) &&
                fabsf(b1) <= 127.f && b1 == rintf(b1)) { vb++; continue; }
            v8++;
        }
        atomicAdd(&votes[0], v8); atomicAdd(&votes[1], v32);
        atomicAdd(&votes[2], vf); atomicAdd(&votes[3], vb);
        __syncthreads();
        if (threadIdx.x == 0) {
            int m = 0;
            for (int j = 1; j < 4; j++) if (votes[j] > votes[m]) m = j;
            g_mode = m;
        }
    } else if (threadIdx.x < 32) {
        int lane = threadIdx.x;
        float a = gua[lane], b = dna[lane];
        unsigned m1 = __ballot_sync(0xffffffffu, a > 0.f && a < 1e-2f);
        unsigned m2 = __ballot_sync(0xffffffffu, b > 0.f && b < 1e-2f);
        if (lane == 0) {
            g_gu_swap = (m1 == 0xffffffffu) ? 0 : 1;
            g_dn_swap = (m2 == 0xffffffffu) ? 0 : 1;
        }
    }
}

// ---------------- 1. routing ----------------
__global__ void routing_kernel(const float* __restrict__ logits) {
    int tid = threadIdx.x;
    if (tid < NT) {
        float v[NE];
#pragma unroll
        for (int j = 0; j < NE; j++) v[j] = logits[tid * NE + j];
        int ids[NK]; float vals[NK];
#pragma unroll
        for (int k = 0; k < NK; k++) {
            int bi = 0; float bv = v[0];
#pragma unroll
            for (int j = 1; j < NE; j++)
                if (v[j] > bv) { bv = v[j]; bi = j; }
            ids[k] = bi; vals[k] = bv; v[bi] = -3.4e38f;
        }
        float m = vals[0], s = 0.f, w[NK];
#pragma unroll
        for (int k = 0; k < NK; k++) { w[k] = expf(vals[k] - m); s += w[k]; }
#pragma unroll
        for (int k = 0; k < NK; k++) {
            g_topk_w[tid * NK + k]  = w[k] / s;
            g_topk_ids[tid * NK + k] = ids[k];
        }
    }
    __syncthreads();
    int wp = tid >> 5, lane = tid & 31;
    if (wp < NE) {
        int cnt = 0;
        for (int base = 0; base < NT * NK; base += 32) {
            int fe = g_topk_ids[base + lane];
            unsigned msk = __ballot_sync(0xffffffffu, fe == wp);
            if (fe == wp) {
                int p = cnt + __popc(msk & ((1u << lane) - 1u));
                g_pos[base + lane] = p;
                if (p < NCAP) {
                    g_row_tok[wp * NCAP + p]  = (base + lane) >> 2;
                    g_row_flat[wp * NCAP + p] = base + lane;
                }
            }
            cnt += __popc(msk);
        }
        if (lane == 0) g_count[wp] = cnt;
    }
}

// ---------------- 2. per-token dynamic int8 quant ----------------
__global__ void quant_x(const float* __restrict__ x) {
    int t = blockIdx.x, tid = threadIdx.x;
    __shared__ float red[256];
    const float* row = x + (size_t)t * NH;
    float mx = 0.f;
    for (int i = tid; i < NH; i += 256) mx = fmaxf(mx, fabsf(row[i]));
    red[tid] = mx; __syncthreads();
    for (int s = 128; s > 0; s >>= 1) { if (tid < s) red[tid] = fmaxf(red[tid], red[tid + s]); __syncthreads(); }
    float sc = red[0] / 127.0f;
    if (tid == 0) g_xscale[t] = sc;
    float sd = (sc > 0.f) ? sc : 1.0f;
    for (int i = tid; i < NH; i += 256) {
        float q = rintf(row[i] / sd);
        q = fminf(fmaxf(q, -127.f), 127.f);
        g_qx[(size_t)t * NH + i] = (int8_t)q;
    }
}

// ---------------- GEMM helpers ----------------
#define MMA_S8(d, a0, a1, a2, a3, b0, b1)                                         \
    asm volatile("mma.sync.aligned.m16n8k32.row.col.s32.s8.s8.s32 "               \
                 "{%0,%1,%2,%3}, {%4,%5,%6,%7}, {%8,%9}, {%0,%1,%2,%3};"          \
                 : "+r"(d[0]), "+r"(d[1]), "+r"(d[2]), "+r"(d[3])                 \
                 : "r"(a0), "r"(a1), "r"(a2), "r"(a3), "r"(b0), "r"(b1))

__device__ __forceinline__ void cpa16(uint32_t dst, const void* src) {
    asm volatile("cp.async.cg.shared.global [%0], [%1], 16;" :: "r"(dst), "l"(src));
}

__device__ __forceinline__ int pack_i32(int4 v) {
    int t0 = __byte_perm(v.x, v.y, 0x0040);
    int t1 = __byte_perm(v.z, v.w, 0x0040);
    return __byte_perm(t0, t1, 0x5410);
}
__device__ __forceinline__ int pack_f32(int4 v) {
    float4 f = *(float4*)&v;
    int a = __float2int_rn(f.x) & 255, b = __float2int_rn(f.y) & 255;
    int c = __float2int_rn(f.z) & 255, d = __float2int_rn(f.w);
    return a | (b << 8) | (c << 16) | (d << 24);
}
__device__ __forceinline__ int pack_bf16(uint2 u) {
    int a = __float2int_rn(__uint_as_float((u.x & 0xFFFFu) << 16)) & 255;
    int b = __float2int_rn(__uint_as_float(u.x & 0xFFFF0000u)) & 255;
    int c = __float2int_rn(__uint_as_float((u.y & 0xFFFFu) << 16)) & 255;
    int d = __float2int_rn(__uint_as_float(u.y & 0xFFFF0000u));
    return a | (b << 8) | (c << 16) | (d << 24);
}

// ---------------- tensor-core grouped int8 GEMM: cp.async 3-stage, BM=128 BN=128 BK=32 ----------------
// One m-block per expert (m0=0; m0=128 safety blocks exit when cnt<=128): weights read ONCE.
// R9-proven schedule per iteration:
//   wait(stage kc) -> sync1 -> [A-frags, issue(kc+2), pack(kc)] -> sync2 -> [B-frags, mma]
// Warp-uniform skip of fully-padded 16-row sub-tiles keeps tensor work ~= real rows.
// EPI==1: A = gathered g_qx rows, epilogue dequant+bias+swiglu -> g_act
// EPI==2: A = g_q2 rows,          epilogue dequant+bias -> g_dn[flat]
template <int NC, int EPI>
__global__ __launch_bounds__(256, 2) void gemm_cp(const void* __restrict__ W,
                                                  const float* __restrict__ sb_a,
                                                  const float* __restrict__ sb_b) {
    const int e  = blockIdx.y >> 1;
    const int m0 = (blockIdx.y & 1) * 128;     // m0=128 blocks: capacity-safety, usually exit
    const int cnt = g_count[e];
    if (m0 >= cnt) return;
    const int n0 = blockIdx.x * 128;
    const int mode = g_mode;

    const int swap = (EPI == 1) ? g_gu_swap : g_dn_swap;
    const float* wsc = swap ? sb_b : sb_a;
    const float* wbi = swap ? sb_a : sb_b;

    extern __shared__ char smem[];
    const uint32_t sbase = (uint32_t)__cvta_generic_to_shared(smem);

    const int tid = threadIdx.x;
    const int lane = tid & 31, wid = tid >> 5;
    const int wm = (wid & 1) * 64, wn = (wid >> 1) * 32;   // warp tile m64 x n32
    const int g = lane >> 2, tg = lane & 3;

    // warp-uniform per-sub-tile liveness (16-row granularity)
    bool live[4];
#pragma unroll
    for (int ma = 0; ma < 4; ma++) live[ma] = (m0 + wm + ma * 16) < cnt;

    // A source: 128 rows x 2 chunks of 16B per stage -> 256 threads, 1 chunk each
    const int aM = tid >> 1, aOff = (tid & 1) * 16;
    const int8_t* aPtr;
    {
        int m = m0 + aM;
        bool val = m < cnt;
        if (EPI == 1) {
            int tok = val ? g_row_tok[e * NCAP + m] : 0;
            aPtr = g_qx + (size_t)tok * NH;
        } else {
            aPtr = g_q2 + (size_t)(e * NCAP + (val ? m : 0)) * NI;
        }
    }
    const size_t ebase = (size_t)e * 2048 * NC;

    auto issue_stage = [&](int s) {
        int buf = s % 3;
        cpa16(sbase + buf * SM_A_STRIDE + aM * 48 + aOff, aPtr + s * 32 + aOff);
        uint32_t bb = sbase + SM_B_OFF + buf * SM_B_STRIDE;
        if (mode == 1 || mode == 2) {
            const int* wp = (const int*)W + ebase + n0;
#pragma unroll
            for (int c2 = 0; c2 < 4; c2++) {
                int idx = tid + c2 * 256, kr = idx >> 5, ne = (idx & 31) * 4;
                cpa16(bb + kr * 512 + ne * 4, wp + (size_t)(s * 32 + kr) * NC + ne);
            }
        } else if (mode == 3) {
            const __nv_bfloat16* wp = (const __nv_bfloat16*)W + ebase + n0;
#pragma unroll
            for (int c2 = 0; c2 < 2; c2++) {
                int idx = tid + c2 * 256, kr = idx >> 4, ne = (idx & 15) * 8;
                cpa16(bb + kr * 256 + ne * 2, wp + (size_t)(s * 32 + kr) * NC + ne);
            }
        } else {
            const int8_t* wp = (const int8_t*)W + ebase + n0;
            int kr = tid >> 3, ne = (tid & 7) * 16;
            cpa16(bb + kr * 128 + ne, wp + (size_t)(s * 32 + kr) * NC + ne);
        }
        asm volatile("cp.async.commit_group;");
    };

    const int kq = tid >> 5, nn = tid & 31;

    // pack raw B stage s -> k-major packed words in packed[s&1] (4x4 byte transpose)
    auto pack_stage = [&](int s) {
        const char* raw = smem + SM_B_OFF + (s % 3) * SM_B_STRIDE;
        int* bp = (int*)(smem + SM_P_OFF) + (s & 1) * SM_P_HALF;
        int r0, r1, r2, r3;
        if (mode == 0) {
            const int* rv = (const int*)raw;
            r0 = rv[(4 * kq + 0) * 32 + nn]; r1 = rv[(4 * kq + 1) * 32 + nn];
            r2 = rv[(4 * kq + 2) * 32 + nn]; r3 = rv[(4 * kq + 3) * 32 + nn];
        } else if (mode == 1) {
            const int4* rv = (const int4*)raw;
            r0 = pack_i32(rv[(4 * kq + 0) * 32 + nn]); r1 = pack_i32(rv[(4 * kq + 1) * 32 + nn]);
            r2 = pack_i32(rv[(4 * kq + 2) * 32 + nn]); r3 = pack_i32(rv[(4 * kq + 3) * 32 + nn]);
        } else if (mode == 2) {
            const int4* rv = (const int4*)raw;
            r0 = pack_f32(rv[(4 * kq + 0) * 32 + nn]); r1 = pack_f32(rv[(4 * kq + 1) * 32 + nn]);
            r2 = pack_f32(rv[(4 * kq + 2) * 32 + nn]); r3 = pack_f32(rv[(4 * kq + 3) * 32 + nn]);
        } else {
            const uint2* rv = (const uint2*)raw;
            r0 = pack_bf16(rv[(4 * kq + 0) * 32 + nn]); r1 = pack_bf16(rv[(4 * kq + 1) * 32 + nn]);
            r2 = pack_bf16(rv[(4 * kq + 2) * 32 + nn]); r3 = pack_bf16(rv[(4 * kq + 3) * 32 + nn]);
        }
        int t0 = __byte_perm(r0, r1, 0x5140);
        int t1 = __byte_perm(r0, r1, 0x7362);
        int t2 = __byte_perm(r2, r3, 0x5140);
        int t3 = __byte_perm(r2, r3, 0x7362);
        *(int4*)&bp[kq * 136 + nn * 4] = make_int4(__byte_perm(t0, t2, 0x5410),
                                                   __byte_perm(t0, t2, 0x7632),
                                                   __byte_perm(t1, t3, 0x5410),
                                                   __byte_perm(t1, t3, 0x7632));
    };

    int acc[4][4][4];
#pragma unroll
    for (int i = 0; i < 4; i++)
#pragma unroll
        for (int j = 0; j < 4; j++)
#pragma unroll
            for (int q = 0; q < 4; q++) acc[i][j][q] = 0;

    issue_stage(0);
    issue_stage(1);

    for (int kc = 0; kc < NKC; kc++) {
        if (kc < NKC - 1) asm volatile("cp.async.wait_group 1;" ::: "memory");
        else             asm volatile("cp.async.wait_group 0;" ::: "memory");
        __syncthreads();   // sync1: stage kc (A+raw B) visible to all threads

        // ---- A fragments (live sub-tiles only; overlaps with pack below) ----
        const int* aSv = (const int*)(smem + (kc % 3) * SM_A_STRIDE);
        int af[4][4];
#pragma unroll
        for (int ma = 0; ma < 4; ma++) {
            if (!live[ma]) continue;
            int mrow = wm + ma * 16 + g;
            af[ma][0] = aSv[mrow * 12 + tg];
            af[ma][1] = aSv[(mrow + 8) * 12 + tg];
            af[ma][2] = aSv[mrow * 12 + tg + 4];
            af[ma][3] = aSv[(mrow + 8) * 12 + tg + 4];
        }

        // ---- refill pipeline early (writes slot (kc+2)%3 != kc%3) ----
        if (kc + 2 < NKC) issue_stage(kc + 2);

        // ---- pack raw B stage kc -> packed[kc&1] ----
        pack_stage(kc);
        __syncthreads();   // sync2: packed tile visible

        // ---- B fragments + mma (dead warps skip entirely) ----
        if (live[0]) {
            const int* bp = (const int*)(smem + SM_P_OFF) + (kc & 1) * SM_P_HALF;
            int bf[4][2];
#pragma unroll
            for (int na = 0; na < 4; na++) {
                bf[na][0] = bp[tg * 136 + wn + na * 8 + g];
                bf[na][1] = bp[(tg + 4) * 136 + wn + na * 8 + g];
            }
#pragma unroll
            for (int ma = 0; ma < 4; ma++) {
                if (!live[ma]) continue;
#pragma unroll
                for (int na = 0; na < 4; na++)
                    MMA_S8(acc[ma][na], af[ma][0], af[ma][1], af[ma][2], af[ma][3],
                           bf[na][0], bf[na][1]);
            }
        }
    }

    // ---- epilogue ----
#pragma unroll
    for (int ma = 0; ma < 4; ma++) {
        int rbase = m0 + wm + ma * 16 + g;
#pragma unroll
        for (int half = 0; half < 2; half++) {
            int r = rbase + half * 8;
            if (r >= cnt) continue;
            int row = e * NCAP + r;
            if (EPI == 1) {
                float xs = g_xscale[g_row_tok[row]];
#pragma unroll
                for (int na = 0; na < 4; na++) {
                    int c = n0 + wn + na * 8 + 2 * tg;
                    float ve = (float)acc[ma][na][half * 2]     * xs * wsc[(size_t)e * NC + c]     + wbi[(size_t)e * NC + c];
                    float vo = (float)acc[ma][na][half * 2 + 1] * xs * wsc[(size_t)e * NC + c + 1] + wbi[(size_t)e * NC + c + 1];
                    float glu = fminf(ve, 7.0f);
                    float lin = fminf(fmaxf(vo, -7.0f), 7.0f);
                    float sg  = 1.0f / (1.0f + expf(-1.702f * glu));
                    g_act[(size_t)row * NI + (c >> 1)] = glu * sg * (lin + 1.0f);
                }
            } else {
                float s2 = g_s2[row];
                int flat = g_row_flat[row];
#pragma unroll
                for (int na = 0; na < 4; na++) {
                    int c = n0 + wn + na * 8 + 2 * tg;
                    float o0 = (float)acc[ma][na][half * 2]     * s2 * wsc[(size_t)e * NC + c]     + wbi[(size_t)e * NC + c];
                    float o1 = (float)acc[ma][na][half * 2 + 1] * s2 * wsc[(size_t)e * NC + c + 1] + wbi[(size_t)e * NC + c + 1];
                    *(float2*)&g_dn[(size_t)flat * NH + c] = make_float2(o0, o1);
                }
            }
        }
    }
}

// ---------------- 4. requant activations ----------------
__global__ void quant_act() {
    int b = blockIdx.x;
    int e = b >> 8, m = b & 255;
    if (m >= g_count[e]) return;
    int tid = threadIdx.x;
    __shared__ float red[256];
    const float* row = &g_act[(size_t)b * NI];
    float mx = 0.f;
    for (int i = tid; i < NI; i += 256) mx = fmaxf(mx, fabsf(row[i]));
    red[tid] = mx; __syncthreads();
    for (int s = 128; s > 0; s >>= 1) { if (tid < s) red[tid] = fmaxf(red[tid], red[tid + s]); __syncthreads(); }
    float sc = red[0] / 127.0f;
    if (tid == 0) g_s2[b] = sc;
    float sd = (sc > 0.f) ? sc : 1.0f;
    for (int i = tid; i < NI; i += 256) {
        float q = rintf(row[i] / sd);
        q = fminf(fmaxf(q, -127.f), 127.f);
        g_q2[(size_t)b * NI + i] = (int8_t)q;
    }
}

// ---------------- 6. weighted gather-combine ----------------
__global__ void combine_kernel(float* __restrict__ out) {
    int t = blockIdx.x, tid = threadIdx.x;
    float w[NK]; int ps[NK];
#pragma unroll
    for (int k = 0; k < NK; k++) { w[k] = g_topk_w[t * NK + k]; ps[k] = g_pos[t * NK + k]; }
    for (int i = tid * 4; i < NH; i += 256 * 4) {
        float4 a = {0.f, 0.f, 0.f, 0.f};
#pragma unroll
        for (int k = 0; k < NK; k++) {
            if (ps[k] < NCAP) {
                float4 d = *(const float4*)&g_dn[(size_t)(t * NK + k) * NH + i];
                a.x += w[k] * d.x; a.y += w[k] * d.y;
                a.z += w[k] * d.z; a.w += w[k] * d.w;
            }
        }
        *(float4*)&out[(size_t)t * NH + i] = a;
    }
}

// ---------------- launch ----------------
extern "C" void kernel_launch(void* const* d_in, const int* in_sizes, int n_in,
                              void* d_out, int out_size) {
    int i_hs = 0, i_rl = 1, i_gu = 2, i_gus = 3, i_gub = 4, i_dn = 5, i_dns = 6, i_dnb = 7;
    if (n_in == 8) {
        int a_gu = -1, b_gu = -1, a_dn = -1, b_dn = -1;
        int hs = -1, rl = -1, gu = -1, dn = -1;
        for (int i = 0; i < n_in; i++) {
            long long s = in_sizes[i];
            if (s == (long long)NT * NH) hs = i;
            else if (s == (long long)NT * NE) rl = i;
            else if (s == (long long)NE * NH * N1) gu = i;
            else if (s == (long long)NE * NI * NH) dn = i;
            else if (s == (long long)NE * N1) { if (a_gu < 0) a_gu = i; else b_gu = i; }
            else if (s == (long long)NE * NH) { if (a_dn < 0) a_dn = i; else b_dn = i; }
        }
        if (hs >= 0 && rl >= 0 && gu >= 0 && dn >= 0 &&
            a_gu >= 0 && b_gu >= 0 && a_dn >= 0 && b_dn >= 0) {
            i_hs = hs; i_rl = rl; i_gu = gu; i_dn = dn;
            i_gus = a_gu; i_gub = b_gu; i_dns = a_dn; i_dnb = b_dn;
        }
    }

    const float* hs    = (const float*)d_in[i_hs];
    const float* rl    = (const float*)d_in[i_rl];
    const void*  gup   = d_in[i_gu];
    const float* gup_a = (const float*)d_in[i_gus];
    const float* gup_b = (const float*)d_in[i_gub];
    const void*  dnw   = d_in[i_dn];
    const float* dn_a  = (const float*)d_in[i_dns];
    const float* dn_b  = (const float*)d_in[i_dnb];
    float* out = (float*)d_out;

    cudaFuncSetAttribute(gemm_cp<N1, 1>, cudaFuncAttributeMaxDynamicSharedMemorySize, SM_TOTAL);
    cudaFuncSetAttribute(gemm_cp<NH, 2>, cudaFuncAttributeMaxDynamicSharedMemorySize, SM_TOTAL);

    prep_kernel<<<2, 256>>>(gup, gup_a, dn_a);                                       // 1
    routing_kernel<<<1, 1024>>>(rl);                                                 // 2
    quant_x<<<NT, 256>>>(hs);                                                        // 3
    gemm_cp<N1, 1><<<dim3(N1 / 128, NE * 2), 256, SM_TOTAL>>>(gup, gup_a, gup_b);    // 4 (profiled)
    quant_act<<<NE * NCAP, 256>>>();                                                 // 5
    gemm_cp<NH, 2><<<dim3(NH / 128, NE * 2), 256, SM_TOTAL>>>(dnw, dn_a, dn_b);      // 6
    combine_kernel<<<NT, 256>>>(out);                                                // 7
}

// round 14
// speedup vs baseline: 1.0813x; 1.0813x over previous
#include <cuda_runtime.h>
#include <cuda_bf16.h>
#include <cstdint>
#include <cstddef>

#define NE   32
#define NK   4
#define NH   2048
#define NI   2048
#define NT   512
#define NCAP 256
#define N1   4096   // 2*I
#define NKC  64     // K / BK, BK = 32

// dynamic smem layout (bytes): BM=128, BN=128, BK=32, 3-stage raw + double packed
#define SM_A_STRIDE 6144      // 128 rows * 48B (padded, conflict-free frag reads)
#define SM_B_OFF    18432     // 3 * SM_A_STRIDE
#define SM_B_STRIDE 16384     // worst-case raw stage: 32k x 128n x 4B
#define SM_P_OFF    67584     // SM_B_OFF + 3 * SM_B_STRIDE
#define SM_P_HALF   1088      // 8 * 136 ints
#define SM_TOTAL    76288     // SM_P_OFF + 2 * 4352

// ---------------- scratch ----------------
__device__ int8_t g_qx[NT * NH];
__device__ float  g_xscale[NT];
__device__ int    g_topk_ids[NT * NK];
__device__ float  g_topk_w[NT * NK];
__device__ int    g_pos[NT * NK];
__device__ int    g_count[NE];
__device__ int    g_row_tok[NE * NCAP];
__device__ int    g_row_flat[NE * NCAP];
__device__ float  g_act[(size_t)NE * NCAP * NI];
__device__ int8_t g_q2[(size_t)NE * NCAP * NI];
__device__ float  g_s2[NE * NCAP];
__device__ float  g_dn[(size_t)NT * NK * NH];

__device__ int    g_mode;      // 0=int8 packed, 1=int32, 2=f32, 3=bf16
__device__ int    g_gu_swap;
__device__ int    g_dn_swap;

// ---------------- 0. detect dtype + classify scale/bias ----------------
__global__ void prep_kernel(const void* __restrict__ w,
                            const float* __restrict__ gua, const float* __restrict__ dna) {
    if (blockIdx.x == 0) {
        __shared__ int votes[4];
        if (threadIdx.x < 4) votes[threadIdx.x] = 0;
        __syncthreads();
        const int* wi = (const int*)w;
        int v8 = 0, v32 = 0, vf = 0, vb = 0;
        for (int i = threadIdx.x; i < 8192; i += 256) {
            int v = wi[i];
            if (v == 0) continue;
            if (v >= -127 && v <= 127) { v32++; continue; }
            float f = __int_as_float(v);
            if (fabsf(f) <= 127.f && f == rintf(f)) { vf++; continue; }
            float b0 = __uint_as_float(((unsigned)v & 0xFFFFu) << 16);
            float b1 = __uint_as_float(((unsigned)v) & 0xFFFF0000u);
            if (fabsf(b0) <= 127.f && b0 == rintf(b0) &&
                fabsf(b1) <= 127.f && b1 == rintf(b1)) { vb++; continue; }
            v8++;
        }
        atomicAdd(&votes[0], v8); atomicAdd(&votes[1], v32);
        atomicAdd(&votes[2], vf); atomicAdd(&votes[3], vb);
        __syncthreads();
        if (threadIdx.x == 0) {
            int m = 0;
            for (int j = 1; j < 4; j++) if (votes[j] > votes[m]) m = j;
            g_mode = m;
        }
    } else if (threadIdx.x < 32) {
        int lane = threadIdx.x;
        float a = gua[lane], b = dna[lane];
        unsigned m1 = __ballot_sync(0xffffffffu, a > 0.f && a < 1e-2f);
        unsigned m2 = __ballot_sync(0xffffffffu, b > 0.f && b < 1e-2f);
        if (lane == 0) {
            g_gu_swap = (m1 == 0xffffffffu) ? 0 : 1;
            g_dn_swap = (m2 == 0xffffffffu) ? 0 : 1;
        }
    }
}

// ---------------- 1. routing ----------------
__global__ void routing_kernel(const float* __restrict__ logits) {
    int tid = threadIdx.x;
    if (tid < NT) {
        float v[NE];
#pragma unroll
        for (int j = 0; j < NE; j++) v[j] = logits[tid * NE + j];
        int ids[NK]; float vals[NK];
#pragma unroll
        for (int k = 0; k < NK; k++) {
            int bi = 0; float bv = v[0];
#pragma unroll
            for (int j = 1; j < NE; j++)
                if (v[j] > bv) { bv = v[j]; bi = j; }
            ids[k] = bi; vals[k] = bv; v[bi] = -3.4e38f;
        }
        float m = vals[0], s = 0.f, w[NK];
#pragma unroll
        for (int k = 0; k < NK; k++) { w[k] = expf(vals[k] - m); s += w[k]; }
#pragma unroll
        for (int k = 0; k < NK; k++) {
            g_topk_w[tid * NK + k]  = w[k] / s;
            g_topk_ids[tid * NK + k] = ids[k];
        }
    }
    __syncthreads();
    int wp = tid >> 5, lane = tid & 31;
    if (wp < NE) {
        int cnt = 0;
        for (int base = 0; base < NT * NK; base += 32) {
            int fe = g_topk_ids[base + lane];
            unsigned msk = __ballot_sync(0xffffffffu, fe == wp);
            if (fe == wp) {
                int p = cnt + __popc(msk & ((1u << lane) - 1u));
                g_pos[base + lane] = p;
                if (p < NCAP) {
                    g_row_tok[wp * NCAP + p]  = (base + lane) >> 2;
                    g_row_flat[wp * NCAP + p] = base + lane;
                }
            }
            cnt += __popc(msk);
        }
        if (lane == 0) g_count[wp] = cnt;
    }
}

// ---------------- 2. per-token dynamic int8 quant ----------------
__global__ void quant_x(const float* __restrict__ x) {
    int t = blockIdx.x, tid = threadIdx.x;
    __shared__ float red[256];
    const float* row = x + (size_t)t * NH;
    float mx = 0.f;
    for (int i = tid; i < NH; i += 256) mx = fmaxf(mx, fabsf(row[i]));
    red[tid] = mx; __syncthreads();
    for (int s = 128; s > 0; s >>= 1) { if (tid < s) red[tid] = fmaxf(red[tid], red[tid + s]); __syncthreads(); }
    float sc = red[0] / 127.0f;
    if (tid == 0) g_xscale[t] = sc;
    float sd = (sc > 0.f) ? sc : 1.0f;
    for (int i = tid; i < NH; i += 256) {
        float q = rintf(row[i] / sd);
        q = fminf(fmaxf(q, -127.f), 127.f);
        g_qx[(size_t)t * NH + i] = (int8_t)q;
    }
}

// ---------------- GEMM helpers ----------------
#define MMA_S8(d, a0, a1, a2, a3, b0, b1)                                         \
    asm volatile("mma.sync.aligned.m16n8k32.row.col.s32.s8.s8.s32 "               \
                 "{%0,%1,%2,%3}, {%4,%5,%6,%7}, {%8,%9}, {%0,%1,%2,%3};"          \
                 : "+r"(d[0]), "+r"(d[1]), "+r"(d[2]), "+r"(d[3])                 \
                 : "r"(a0), "r"(a1), "r"(a2), "r"(a3), "r"(b0), "r"(b1))

__device__ __forceinline__ void cpa16(uint32_t dst, const void* src) {
    asm volatile("cp.async.cg.shared.global [%0], [%1], 16;" :: "r"(dst), "l"(src));
}

__device__ __forceinline__ int pack_i32(int4 v) {
    int t0 = __byte_perm(v.x, v.y, 0x0040);
    int t1 = __byte_perm(v.z, v.w, 0x0040);
    return __byte_perm(t0, t1, 0x5410);
}
__device__ __forceinline__ int pack_f32(int4 v) {
    float4 f = *(float4*)&v;
    int a = __float2int_rn(f.x) & 255, b = __float2int_rn(f.y) & 255;
    int c = __float2int_rn(f.z) & 255, d = __float2int_rn(f.w);
    return a | (b << 8) | (c << 16) | (d << 24);
}
__device__ __forceinline__ int pack_bf16(uint2 u) {
    int a = __float2int_rn(__uint_as_float((u.x & 0xFFFFu) << 16)) & 255;
    int b = __float2int_rn(__uint_as_float(u.x & 0xFFFF0000u)) & 255;
    int c = __float2int_rn(__uint_as_float((u.y & 0xFFFFu) << 16)) & 255;
    int d = __float2int_rn(__uint_as_float(u.y & 0xFFFF0000u));
    return a | (b << 8) | (c << 16) | (d << 24);
}

// ---------------- tensor-core grouped int8 GEMM: cp.async 3-stage, BM=128 BN=128 BK=32 ----------------
// One m-block per expert: weights read ONCE. SMSP-balanced warp mapping:
//   warp wid owns m-sub-tiles {wid&3, (wid&3)+4} (16 rows each, interleaved stride 64)
//   and n-group (wid>>2)*64. Live rows (cnt~64 -> sub-tiles 0..3) spread over ALL SMSPs.
// R9-proven schedule: wait(kc) -> sync1 -> [issue(kc+2), pack(kc)] -> sync2 -> [frags, mma]
// EPI==1: A = gathered g_qx rows, epilogue dequant+bias+swiglu -> g_act
// EPI==2: A = g_q2 rows,          epilogue dequant+bias -> g_dn[flat]
template <int NC, int EPI>
__global__ __launch_bounds__(256, 2) void gemm_cp(const void* __restrict__ W,
                                                  const float* __restrict__ sb_a,
                                                  const float* __restrict__ sb_b) {
    const int e  = blockIdx.y >> 1;
    const int m0 = (blockIdx.y & 1) * 128;     // m0=128: capacity safety, usually exits
    const int cnt = g_count[e];
    if (m0 >= cnt) return;
    const int n0 = blockIdx.x * 128;
    const int mode = g_mode;

    const int swap = (EPI == 1) ? g_gu_swap : g_dn_swap;
    const float* wsc = swap ? sb_b : sb_a;
    const float* wbi = swap ? sb_a : sb_b;

    extern __shared__ char smem[];
    const uint32_t sbase = (uint32_t)__cvta_generic_to_shared(smem);

    const int tid = threadIdx.x;
    const int lane = tid & 31, wid = tid >> 5;
    const int msel = wid & 3;                  // SMSP-aligned m-interleave
    const int wn = (wid >> 2) * 64;            // n-group: 64 cols, 8 MMAs
    const int g = lane >> 2, tg = lane & 3;

    // warp-uniform sub-tile liveness: sub-tile rows = (msel + 4*ma)*16
    bool live[2];
#pragma unroll
    for (int ma = 0; ma < 2; ma++) live[ma] = (m0 + (msel + 4 * ma) * 16) < cnt;

    // A source: 128 rows x 2 chunks of 16B per stage -> 256 threads, 1 chunk each
    const int aM = tid >> 1, aOff = (tid & 1) * 16;
    const int8_t* aPtr;
    {
        int m = m0 + aM;
        bool val = m < cnt;
        if (EPI == 1) {
            int tok = val ? g_row_tok[e * NCAP + m] : 0;
            aPtr = g_qx + (size_t)tok * NH;
        } else {
            aPtr = g_q2 + (size_t)(e * NCAP + (val ? m : 0)) * NI;
        }
    }
    const size_t ebase = (size_t)e * 2048 * NC;

    auto issue_stage = [&](int s) {
        int buf = s % 3;
        cpa16(sbase + buf * SM_A_STRIDE + aM * 48 + aOff, aPtr + s * 32 + aOff);
        uint32_t bb = sbase + SM_B_OFF + buf * SM_B_STRIDE;
        if (mode == 1 || mode == 2) {
            const int* wp = (const int*)W + ebase + n0;
#pragma unroll
            for (int c2 = 0; c2 < 4; c2++) {
                int idx = tid + c2 * 256, kr = idx >> 5, ne = (idx & 31) * 4;
                cpa16(bb + kr * 512 + ne * 4, wp + (size_t)(s * 32 + kr) * NC + ne);
            }
        } else if (mode == 3) {
            const __nv_bfloat16* wp = (const __nv_bfloat16*)W + ebase + n0;
#pragma unroll
            for (int c2 = 0; c2 < 2; c2++) {
                int idx = tid + c2 * 256, kr = idx >> 4, ne = (idx & 15) * 8;
                cpa16(bb + kr * 256 + ne * 2, wp + (size_t)(s * 32 + kr) * NC + ne);
            }
        } else {
            const int8_t* wp = (const int8_t*)W + ebase + n0;
            int kr = tid >> 3, ne = (tid & 7) * 16;
            cpa16(bb + kr * 128 + ne, wp + (size_t)(s * 32 + kr) * NC + ne);
        }
        asm volatile("cp.async.commit_group;");
    };

    const int kq = tid >> 5, nn = tid & 31;

    // pack raw B stage s -> k-major packed words in packed[s&1] (4x4 byte transpose)
    auto pack_stage = [&](int s) {
        const char* raw = smem + SM_B_OFF + (s % 3) * SM_B_STRIDE;
        int* bp = (int*)(smem + SM_P_OFF) + (s & 1) * SM_P_HALF;
        int r0, r1, r2, r3;
        if (mode == 0) {
            const int* rv = (const int*)raw;
            r0 = rv[(4 * kq + 0) * 32 + nn]; r1 = rv[(4 * kq + 1) * 32 + nn];
            r2 = rv[(4 * kq + 2) * 32 + nn]; r3 = rv[(4 * kq + 3) * 32 + nn];
        } else if (mode == 1) {
            const int4* rv = (const int4*)raw;
            r0 = pack_i32(rv[(4 * kq + 0) * 32 + nn]); r1 = pack_i32(rv[(4 * kq + 1) * 32 + nn]);
            r2 = pack_i32(rv[(4 * kq + 2) * 32 + nn]); r3 = pack_i32(rv[(4 * kq + 3) * 32 + nn]);
        } else if (mode == 2) {
            const int4* rv = (const int4*)raw;
            r0 = pack_f32(rv[(4 * kq + 0) * 32 + nn]); r1 = pack_f32(rv[(4 * kq + 1) * 32 + nn]);
            r2 = pack_f32(rv[(4 * kq + 2) * 32 + nn]); r3 = pack_f32(rv[(4 * kq + 3) * 32 + nn]);
        } else {
            const uint2* rv = (const uint2*)raw;
            r0 = pack_bf16(rv[(4 * kq + 0) * 32 + nn]); r1 = pack_bf16(rv[(4 * kq + 1) * 32 + nn]);
            r2 = pack_bf16(rv[(4 * kq + 2) * 32 + nn]); r3 = pack_bf16(rv[(4 * kq + 3) * 32 + nn]);
        }
        int t0 = __byte_perm(r0, r1, 0x5140);
        int t1 = __byte_perm(r0, r1, 0x7362);
        int t2 = __byte_perm(r2, r3, 0x5140);
        int t3 = __byte_perm(r2, r3, 0x7362);
        *(int4*)&bp[kq * 136 + nn * 4] = make_int4(__byte_perm(t0, t2, 0x5410),
                                                   __byte_perm(t0, t2, 0x7632),
                                                   __byte_perm(t1, t3, 0x5410),
                                                   __byte_perm(t1, t3, 0x7632));
    };

    int acc[2][8][4];
#pragma unroll
    for (int i = 0; i < 2; i++)
#pragma unroll
        for (int j = 0; j < 8; j++)
#pragma unroll
            for (int q = 0; q < 4; q++) acc[i][j][q] = 0;

    issue_stage(0);
    issue_stage(1);

    for (int kc = 0; kc < NKC; kc++) {
        if (kc < NKC - 1) asm volatile("cp.async.wait_group 1;" ::: "memory");
        else             asm volatile("cp.async.wait_group 0;" ::: "memory");
        __syncthreads();   // sync1: stage kc (A+raw B) visible to all threads

        // ---- refill pipeline early (writes slot (kc+2)%3 != kc%3) ----
        if (kc + 2 < NKC) issue_stage(kc + 2);

        // ---- pack raw B stage kc -> packed[kc&1] ----
        pack_stage(kc);
        __syncthreads();   // sync2: packed tile visible

        // ---- fragments + mma (per-sub-tile skip; af transient to limit regs) ----
        if (live[0]) {
            const int* aSv = (const int*)(smem + (kc % 3) * SM_A_STRIDE);
            const int* bp  = (const int*)(smem + SM_P_OFF) + (kc & 1) * SM_P_HALF;
            int bf[8][2];
#pragma unroll
            for (int na = 0; na < 8; na++) {
                bf[na][0] = bp[tg * 136 + wn + na * 8 + g];
                bf[na][1] = bp[(tg + 4) * 136 + wn + na * 8 + g];
            }
#pragma unroll
            for (int ma = 0; ma < 2; ma++) {
                if (!live[ma]) continue;
                int mrow = (msel + 4 * ma) * 16 + g;
                int a0 = aSv[mrow * 12 + tg];
                int a1 = aSv[(mrow + 8) * 12 + tg];
                int a2 = aSv[mrow * 12 + tg + 4];
                int a3 = aSv[(mrow + 8) * 12 + tg + 4];
#pragma unroll
                for (int na = 0; na < 8; na++)
                    MMA_S8(acc[ma][na], a0, a1, a2, a3, bf[na][0], bf[na][1]);
            }
        }
    }

    // ---- epilogue ----
#pragma unroll
    for (int ma = 0; ma < 2; ma++) {
        int rbase = m0 + (msel + 4 * ma) * 16 + g;
#pragma unroll
        for (int half = 0; half < 2; half++) {
            int r = rbase + half * 8;
            if (r >= cnt) continue;
            int row = e * NCAP + r;
            if (EPI == 1) {
                float xs = g_xscale[g_row_tok[row]];
#pragma unroll
                for (int na = 0; na < 8; na++) {
                    int c = n0 + wn + na * 8 + 2 * tg;
                    float ve = (float)acc[ma][na][half * 2]     * xs * wsc[(size_t)e * NC + c]     + wbi[(size_t)e * NC + c];
                    float vo = (float)acc[ma][na][half * 2 + 1] * xs * wsc[(size_t)e * NC + c + 1] + wbi[(size_t)e * NC + c + 1];
                    float glu = fminf(ve, 7.0f);
                    float lin = fminf(fmaxf(vo, -7.0f), 7.0f);
                    float sg  = 1.0f / (1.0f + expf(-1.702f * glu));
                    g_act[(size_t)row * NI + (c >> 1)] = glu * sg * (lin + 1.0f);
                }
            } else {
                float s2 = g_s2[row];
                int flat = g_row_flat[row];
#pragma unroll
                for (int na = 0; na < 8; na++) {
                    int c = n0 + wn + na * 8 + 2 * tg;
                    float o0 = (float)acc[ma][na][half * 2]     * s2 * wsc[(size_t)e * NC + c]     + wbi[(size_t)e * NC + c];
                    float o1 = (float)acc[ma][na][half * 2 + 1] * s2 * wsc[(size_t)e * NC + c + 1] + wbi[(size_t)e * NC + c + 1];
                    *(float2*)&g_dn[(size_t)flat * NH + c] = make_float2(o0, o1);
                }
            }
        }
    }
}

// ---------------- 4. requant activations ----------------
__global__ void quant_act() {
    int b = blockIdx.x;
    int e = b >> 8, m = b & 255;
    if (m >= g_count[e]) return;
    int tid = threadIdx.x;
    __shared__ float red[256];
    const float* row = &g_act[(size_t)b * NI];
    float mx = 0.f;
    for (int i = tid; i < NI; i += 256) mx = fmaxf(mx, fabsf(row[i]));
    red[tid] = mx; __syncthreads();
    for (int s = 128; s > 0; s >>= 1) { if (tid < s) red[tid] = fmaxf(red[tid], red[tid + s]); __syncthreads(); }
    float sc = red[0] / 127.0f;
    if (tid == 0) g_s2[b] = sc;
    float sd = (sc > 0.f) ? sc : 1.0f;
    for (int i = tid; i < NI; i += 256) {
        float q = rintf(row[i] / sd);
        q = fminf(fmaxf(q, -127.f), 127.f);
        g_q2[(size_t)b * NI + i] = (int8_t)q;
    }
}

// ---------------- 6. weighted gather-combine ----------------
__global__ void combine_kernel(float* __restrict__ out) {
    int t = blockIdx.x, tid = threadIdx.x;
    float w[NK]; int ps[NK];
#pragma unroll
    for (int k = 0; k < NK; k++) { w[k] = g_topk_w[t * NK + k]; ps[k] = g_pos[t * NK + k]; }
    for (int i = tid * 4; i < NH; i += 256 * 4) {
        float4 a = {0.f, 0.f, 0.f, 0.f};
#pragma unroll
        for (int k = 0; k < NK; k++) {
            if (ps[k] < NCAP) {
                float4 d = *(const float4*)&g_dn[(size_t)(t * NK + k) * NH + i];
                a.x += w[k] * d.x; a.y += w[k] * d.y;
                a.z += w[k] * d.z; a.w += w[k] * d.w;
            }
        }
        *(float4*)&out[(size_t)t * NH + i] = a;
    }
}

// ---------------- launch ----------------
extern "C" void kernel_launch(void* const* d_in, const int* in_sizes, int n_in,
                              void* d_out, int out_size) {
    int i_hs = 0, i_rl = 1, i_gu = 2, i_gus = 3, i_gub = 4, i_dn = 5, i_dns = 6, i_dnb = 7;
    if (n_in == 8) {
        int a_gu = -1, b_gu = -1, a_dn = -1, b_dn = -1;
        int hs = -1, rl = -1, gu = -1, dn = -1;
        for (int i = 0; i < n_in; i++) {
            long long s = in_sizes[i];
            if (s == (long long)NT * NH) hs = i;
            else if (s == (long long)NT * NE) rl = i;
            else if (s == (long long)NE * NH * N1) gu = i;
            else if (s == (long long)NE * NI * NH) dn = i;
            else if (s == (long long)NE * N1) { if (a_gu < 0) a_gu = i; else b_gu = i; }
            else if (s == (long long)NE * NH) { if (a_dn < 0) a_dn = i; else b_dn = i; }
        }
        if (hs >= 0 && rl >= 0 && gu >= 0 && dn >= 0 &&
            a_gu >= 0 && b_gu >= 0 && a_dn >= 0 && b_dn >= 0) {
            i_hs = hs; i_rl = rl; i_gu = gu; i_dn = dn;
            i_gus = a_gu; i_gub = b_gu; i_dns = a_dn; i_dnb = b_dn;
        }
    }

    const float* hs    = (const float*)d_in[i_hs];
    const float* rl    = (const float*)d_in[i_rl];
    const void*  gup   = d_in[i_gu];
    const float* gup_a = (const float*)d_in[i_gus];
    const float* gup_b = (const float*)d_in[i_gub];
    const void*  dnw   = d_in[i_dn];
    const float* dn_a  = (const float*)d_in[i_dns];
    const float* dn_b  = (const float*)d_in[i_dnb];
    float* out = (float*)d_out;

    cudaFuncSetAttribute(gemm_cp<N1, 1>, cudaFuncAttributeMaxDynamicSharedMemorySize, SM_TOTAL);
    cudaFuncSetAttribute(gemm_cp<NH, 2>, cudaFuncAttributeMaxDynamicSharedMemorySize, SM_TOTAL);

    prep_kernel<<<2, 256>>>(gup, gup_a, dn_a);                                       // 1
    routing_kernel<<<1, 1024>>>(rl);                                                 // 2
    quant_x<<<NT, 256>>>(hs);                                                        // 3
    gemm_cp<N1, 1><<<dim3(N1 / 128, NE * 2), 256, SM_TOTAL>>>(gup, gup_a, gup_b);    // 4 (profiled)
    quant_act<<<NE * NCAP, 256>>>();                                                 // 5
    gemm_cp<NH, 2><<<dim3(NH / 128, NE * 2), 256, SM_TOTAL>>>(dnw, dn_a, dn_b);      // 6
    combine_kernel<<<NT, 256>>>(out);                                                // 7
}

// round 15
// speedup vs baseline: 1.3810x; 1.2772x over previous
#include <cuda_runtime.h>
#include <cuda_bf16.h>
#include <cstdint>
#include <cstddef>

#define NE   32
#define NK   4
#define NH   2048
#define NI   2048
#define NT   512
#define NCAP 256
#define N1   4096   // 2*I
#define NKC  64     // K / BK, BK = 32

// dynamic smem layout (bytes): BM=96, BN=128, BK=32, 3-stage raw + double packed
#define SM_A_STRIDE 4608      // 96 rows * 48B (padded rows: conflict-free frag reads)
#define SM_B_OFF    13824     // 3 * SM_A_STRIDE
#define SM_B_STRIDE 16384     // worst-case raw stage: 32k x 128n x 4B
#define SM_P_OFF    62976     // SM_B_OFF + 3 * SM_B_STRIDE
#define SM_P_HALF   1088      // 8 * 136 ints
#define SM_TOTAL    71680     // SM_P_OFF + 2 * 4352

// ---------------- scratch ----------------
__device__ int8_t g_qx[NT * NH];
__device__ float  g_xscale[NT];
__device__ int    g_topk_ids[NT * NK];
__device__ float  g_topk_w[NT * NK];
__device__ int    g_pos[NT * NK];
__device__ int    g_count[NE];
__device__ int    g_row_tok[NE * NCAP];
__device__ int    g_row_flat[NE * NCAP];
__device__ float  g_act[(size_t)NE * NCAP * NI];
__device__ int8_t g_q2[(size_t)NE * NCAP * NI];
__device__ float  g_s2[NE * NCAP];
__device__ float  g_dn[(size_t)NT * NK * NH];

__device__ int    g_mode;      // 0=int8 packed, 1=int32, 2=f32, 3=bf16
__device__ int    g_gu_swap;
__device__ int    g_dn_swap;

// ---------------- 0. detect dtype + classify scale/bias ----------------
__global__ void prep_kernel(const void* __restrict__ w,
                            const float* __restrict__ gua, const float* __restrict__ dna) {
    if (blockIdx.x == 0) {
        __shared__ int votes[4];
        if (threadIdx.x < 4) votes[threadIdx.x] = 0;
        __syncthreads();
        const int* wi = (const int*)w;
        int v8 = 0, v32 = 0, vf = 0, vb = 0;
        for (int i = threadIdx.x; i < 8192; i += 256) {
            int v = wi[i];
            if (v == 0) continue;
            if (v >= -127 && v <= 127) { v32++; continue; }
            float f = __int_as_float(v);
            if (fabsf(f) <= 127.f && f == rintf(f)) { vf++; continue; }
            float b0 = __uint_as_float(((unsigned)v & 0xFFFFu) << 16);
            float b1 = __uint_as_float(((unsigned)v) & 0xFFFF0000u);
            if (fabsf(b0) <= 127.f && b0 == rintf(b0) &&
                fabsf(b1) <= 127.f && b1 == rintf(b1)) { vb++; continue; }
            v8++;
        }
        atomicAdd(&votes[0], v8); atomicAdd(&votes[1], v32);
        atomicAdd(&votes[2], vf); atomicAdd(&votes[3], vb);
        __syncthreads();
        if (threadIdx.x == 0) {
            int m = 0;
            for (int j = 1; j < 4; j++) if (votes[j] > votes[m]) m = j;
            g_mode = m;
        }
    } else if (threadIdx.x < 32) {
        int lane = threadIdx.x;
        float a = gua[lane], b = dna[lane];
        unsigned m1 = __ballot_sync(0xffffffffu, a > 0.f && a < 1e-2f);
        unsigned m2 = __ballot_sync(0xffffffffu, b > 0.f && b < 1e-2f);
        if (lane == 0) {
            g_gu_swap = (m1 == 0xffffffffu) ? 0 : 1;
            g_dn_swap = (m2 == 0xffffffffu) ? 0 : 1;
        }
    }
}

// ---------------- 1. routing ----------------
__global__ void routing_kernel(const float* __restrict__ logits) {
    int tid = threadIdx.x;
    if (tid < NT) {
        float v[NE];
#pragma unroll
        for (int j = 0; j < NE; j++) v[j] = logits[tid * NE + j];
        int ids[NK]; float vals[NK];
#pragma unroll
        for (int k = 0; k < NK; k++) {
            int bi = 0; float bv = v[0];
#pragma unroll
            for (int j = 1; j < NE; j++)
                if (v[j] > bv) { bv = v[j]; bi = j; }
            ids[k] = bi; vals[k] = bv; v[bi] = -3.4e38f;
        }
        float m = vals[0], s = 0.f, w[NK];
#pragma unroll
        for (int k = 0; k < NK; k++) { w[k] = expf(vals[k] - m); s += w[k]; }
#pragma unroll
        for (int k = 0; k < NK; k++) {
            g_topk_w[tid * NK + k]  = w[k] / s;
            g_topk_ids[tid * NK + k] = ids[k];
        }
    }
    __syncthreads();
    int wp = tid >> 5, lane = tid & 31;
    if (wp < NE) {
        int cnt = 0;
        for (int base = 0; base < NT * NK; base += 32) {
            int fe = g_topk_ids[base + lane];
            unsigned msk = __ballot_sync(0xffffffffu, fe == wp);
            if (fe == wp) {
                int p = cnt + __popc(msk & ((1u << lane) - 1u));
                g_pos[base + lane] = p;
                if (p < NCAP) {
                    g_row_tok[wp * NCAP + p]  = (base + lane) >> 2;
                    g_row_flat[wp * NCAP + p] = base + lane;
                }
            }
            cnt += __popc(msk);
        }
        if (lane == 0) g_count[wp] = cnt;
    }
}

// ---------------- 2. per-token dynamic int8 quant ----------------
__global__ void quant_x(const float* __restrict__ x) {
    int t = blockIdx.x, tid = threadIdx.x;
    __shared__ float red[256];
    const float* row = x + (size_t)t * NH;
    float mx = 0.f;
    for (int i = tid; i < NH; i += 256) mx = fmaxf(mx, fabsf(row[i]));
    red[tid] = mx; __syncthreads();
    for (int s = 128; s > 0; s >>= 1) { if (tid < s) red[tid] = fmaxf(red[tid], red[tid + s]); __syncthreads(); }
    float sc = red[0] / 127.0f;
    if (tid == 0) g_xscale[t] = sc;
    float sd = (sc > 0.f) ? sc : 1.0f;
    for (int i = tid; i < NH; i += 256) {
        float q = rintf(row[i] / sd);
        q = fminf(fmaxf(q, -127.f), 127.f);
        g_qx[(size_t)t * NH + i] = (int8_t)q;
    }
}

// ---------------- GEMM helpers ----------------
#define MMA_S8(d, a0, a1, a2, a3, b0, b1)                                         \
    asm volatile("mma.sync.aligned.m16n8k32.row.col.s32.s8.s8.s32 "               \
                 "{%0,%1,%2,%3}, {%4,%5,%6,%7}, {%8,%9}, {%0,%1,%2,%3};"          \
                 : "+r"(d[0]), "+r"(d[1]), "+r"(d[2]), "+r"(d[3])                 \
                 : "r"(a0), "r"(a1), "r"(a2), "r"(a3), "r"(b0), "r"(b1))

__device__ __forceinline__ void cpa16(uint32_t dst, const void* src) {
    asm volatile("cp.async.cg.shared.global [%0], [%1], 16;" :: "r"(dst), "l"(src));
}

__device__ __forceinline__ int pack_i32(int4 v) {
    int t0 = __byte_perm(v.x, v.y, 0x0040);
    int t1 = __byte_perm(v.z, v.w, 0x0040);
    return __byte_perm(t0, t1, 0x5410);
}
__device__ __forceinline__ int pack_f32(int4 v) {
    float4 f = *(float4*)&v;
    int a = __float2int_rn(f.x) & 255, b = __float2int_rn(f.y) & 255;
    int c = __float2int_rn(f.z) & 255, d = __float2int_rn(f.w);
    return a | (b << 8) | (c << 16) | (d << 24);
}
__device__ __forceinline__ int pack_bf16(uint2 u) {
    int a = __float2int_rn(__uint_as_float((u.x & 0xFFFFu) << 16)) & 255;
    int b = __float2int_rn(__uint_as_float(u.x & 0xFFFF0000u)) & 255;
    int c = __float2int_rn(__uint_as_float((u.y & 0xFFFFu) << 16)) & 255;
    int d = __float2int_rn(__uint_as_float(u.y & 0xFFFF0000u));
    return a | (b << 8) | (c << 16) | (d << 24);
}

// ---------------- tensor-core grouped int8 GEMM: cp.async 3-stage, BM=96 BN=128 BK=32 ----------------
// One 96-row m-block covers cnt~64 experts: B read ONCE, fewer blocks, 3 CTAs/SM preserved.
// Warp map: n-group (wid>>1)*32; m-sub-tiles {msel, msel+2, msel+4}, msel=wid&1
//   -> for cnt<=64 every warp has exactly 2 live sub-tiles (SMSP-balanced).
// R9-proven schedule: wait(kc) -> sync1 -> pack(kc) -> issue(kc+2) -> sync2 -> frags+mma.
// EPI==1: A = gathered g_qx rows, epilogue dequant+bias+swiglu -> g_act
// EPI==2: A = g_q2 rows,          epilogue dequant+bias -> g_dn[flat]
template <int NC, int EPI>
__global__ __launch_bounds__(256, 3) void gemm_cp(const void* __restrict__ W,
                                                  const float* __restrict__ sb_a,
                                                  const float* __restrict__ sb_b) {
    const int e  = blockIdx.y / 3;
    const int m0 = (blockIdx.y % 3) * 96;      // m0=96,192: capacity safety, usually exit
    const int cnt = g_count[e];
    if (m0 >= cnt) return;
    const int n0 = blockIdx.x * 128;
    const int mode = g_mode;

    const int swap = (EPI == 1) ? g_gu_swap : g_dn_swap;
    const float* wsc = swap ? sb_b : sb_a;
    const float* wbi = swap ? sb_a : sb_b;

    extern __shared__ char smem[];
    const uint32_t sbase = (uint32_t)__cvta_generic_to_shared(smem);

    const int tid = threadIdx.x;
    const int lane = tid & 31, wid = tid >> 5;
    const int msel = wid & 1;                  // m interleave (sub-tiles msel, msel+2, msel+4)
    const int wn = (wid >> 1) * 32;            // n-group: 32 cols, 4 MMAs
    const int g = lane >> 2, tg = lane & 3;

    // warp-uniform sub-tile liveness (16-row granularity)
    bool live[3];
#pragma unroll
    for (int j = 0; j < 3; j++) live[j] = (m0 + (msel + 2 * j) * 16) < cnt;

    // A source: 96 rows x 2 chunks of 16B per stage -> threads 0..191
    const int aM = tid >> 1, aOff = (tid & 1) * 16;
    const int8_t* aPtr = nullptr;
    if (tid < 192) {
        int m = m0 + aM;
        bool val = m < cnt;
        if (EPI == 1) {
            int tok = val ? g_row_tok[e * NCAP + m] : 0;
            aPtr = g_qx + (size_t)tok * NH;
        } else {
            aPtr = g_q2 + (size_t)(e * NCAP + (val ? m : 0)) * NI;
        }
    }
    const size_t ebase = (size_t)e * 2048 * NC;

    auto issue_stage = [&](int s) {
        int buf = s % 3;
        if (tid < 192)
            cpa16(sbase + buf * SM_A_STRIDE + aM * 48 + aOff, aPtr + s * 32 + aOff);
        uint32_t bb = sbase + SM_B_OFF + buf * SM_B_STRIDE;
        if (mode == 1 || mode == 2) {
            const int* wp = (const int*)W + ebase + n0;
#pragma unroll
            for (int c2 = 0; c2 < 4; c2++) {
                int idx = tid + c2 * 256, kr = idx >> 5, ne = (idx & 31) * 4;
                cpa16(bb + kr * 512 + ne * 4, wp + (size_t)(s * 32 + kr) * NC + ne);
            }
        } else if (mode == 3) {
            const __nv_bfloat16* wp = (const __nv_bfloat16*)W + ebase + n0;
#pragma unroll
            for (int c2 = 0; c2 < 2; c2++) {
                int idx = tid + c2 * 256, kr = idx >> 4, ne = (idx & 15) * 8;
                cpa16(bb + kr * 256 + ne * 2, wp + (size_t)(s * 32 + kr) * NC + ne);
            }
        } else {
            const int8_t* wp = (const int8_t*)W + ebase + n0;
            int kr = tid >> 3, ne = (tid & 7) * 16;
            cpa16(bb + kr * 128 + ne, wp + (size_t)(s * 32 + kr) * NC + ne);
        }
        asm volatile("cp.async.commit_group;");
    };

    const int kq = tid >> 5, nn = tid & 31;

    // pack raw B stage s -> k-major packed words in packed[s&1] (4x4 byte transpose)
    auto pack_stage = [&](int s) {
        const char* raw = smem + SM_B_OFF + (s % 3) * SM_B_STRIDE;
        int* bp = (int*)(smem + SM_P_OFF) + (s & 1) * SM_P_HALF;
        int r0, r1, r2, r3;
        if (mode == 0) {
            const int* rv = (const int*)raw;
            r0 = rv[(4 * kq + 0) * 32 + nn]; r1 = rv[(4 * kq + 1) * 32 + nn];
            r2 = rv[(4 * kq + 2) * 32 + nn]; r3 = rv[(4 * kq + 3) * 32 + nn];
        } else if (mode == 1) {
            const int4* rv = (const int4*)raw;
            r0 = pack_i32(rv[(4 * kq + 0) * 32 + nn]); r1 = pack_i32(rv[(4 * kq + 1) * 32 + nn]);
            r2 = pack_i32(rv[(4 * kq + 2) * 32 + nn]); r3 = pack_i32(rv[(4 * kq + 3) * 32 + nn]);
        } else if (mode == 2) {
            const int4* rv = (const int4*)raw;
            r0 = pack_f32(rv[(4 * kq + 0) * 32 + nn]); r1 = pack_f32(rv[(4 * kq + 1) * 32 + nn]);
            r2 = pack_f32(rv[(4 * kq + 2) * 32 + nn]); r3 = pack_f32(rv[(4 * kq + 3) * 32 + nn]);
        } else {
            const uint2* rv = (const uint2*)raw;
            r0 = pack_bf16(rv[(4 * kq + 0) * 32 + nn]); r1 = pack_bf16(rv[(4 * kq + 1) * 32 + nn]);
            r2 = pack_bf16(rv[(4 * kq + 2) * 32 + nn]); r3 = pack_bf16(rv[(4 * kq + 3) * 32 + nn]);
        }
        int t0 = __byte_perm(r0, r1, 0x5140);
        int t1 = __byte_perm(r0, r1, 0x7362);
        int t2 = __byte_perm(r2, r3, 0x5140);
        int t3 = __byte_perm(r2, r3, 0x7362);
        *(int4*)&bp[kq * 136 + nn * 4] = make_int4(__byte_perm(t0, t2, 0x5410),
                                                   __byte_perm(t0, t2, 0x7632),
                                                   __byte_perm(t1, t3, 0x5410),
                                                   __byte_perm(t1, t3, 0x7632));
    };

    int acc[3][4][4];
#pragma unroll
    for (int i = 0; i < 3; i++)
#pragma unroll
        for (int j = 0; j < 4; j++)
#pragma unroll
            for (int q = 0; q < 4; q++) acc[i][j][q] = 0;

    issue_stage(0);
    issue_stage(1);

    for (int kc = 0; kc < NKC; kc++) {
        if (kc < NKC - 1) asm volatile("cp.async.wait_group 1;" ::: "memory");
        else             asm volatile("cp.async.wait_group 0;" ::: "memory");
        __syncthreads();   // sync1: stage kc (A+raw B) visible to all threads

        // ---- pack raw B stage kc -> packed[kc&1] ----
        pack_stage(kc);

        // ---- refill pipeline (writes slot (kc+2)%3 != kc%3) ----
        if (kc + 2 < NKC) issue_stage(kc + 2);
        __syncthreads();   // sync2: packed tile visible

        // ---- fragments + mma (per-sub-tile skip) ----
        const int* aSv = (const int*)(smem + (kc % 3) * SM_A_STRIDE);
        const int* bp  = (const int*)(smem + SM_P_OFF) + (kc & 1) * SM_P_HALF;
        int bf[4][2];
#pragma unroll
        for (int na = 0; na < 4; na++) {
            bf[na][0] = bp[tg * 136 + wn + na * 8 + g];
            bf[na][1] = bp[(tg + 4) * 136 + wn + na * 8 + g];
        }
#pragma unroll
        for (int ma = 0; ma < 3; ma++) {
            if (!live[ma]) continue;
            int mrow = (msel + 2 * ma) * 16 + g;
            int a0 = aSv[mrow * 12 + tg];
            int a1 = aSv[(mrow + 8) * 12 + tg];
            int a2 = aSv[mrow * 12 + tg + 4];
            int a3 = aSv[(mrow + 8) * 12 + tg + 4];
#pragma unroll
            for (int na = 0; na < 4; na++)
                MMA_S8(acc[ma][na], a0, a1, a2, a3, bf[na][0], bf[na][1]);
        }
    }

    // ---- epilogue ----
#pragma unroll
    for (int ma = 0; ma < 3; ma++) {
        int rbase = m0 + (msel + 2 * ma) * 16 + g;
#pragma unroll
        for (int half = 0; half < 2; half++) {
            int r = rbase + half * 8;
            if (r >= cnt) continue;
            int row = e * NCAP + r;
            if (EPI == 1) {
                float xs = g_xscale[g_row_tok[row]];
#pragma unroll
                for (int na = 0; na < 4; na++) {
                    int c = n0 + wn + na * 8 + 2 * tg;
                    float ve = (float)acc[ma][na][half * 2]     * xs * wsc[(size_t)e * NC + c]     + wbi[(size_t)e * NC + c];
                    float vo = (float)acc[ma][na][half * 2 + 1] * xs * wsc[(size_t)e * NC + c + 1] + wbi[(size_t)e * NC + c + 1];
                    float glu = fminf(ve, 7.0f);
                    float lin = fminf(fmaxf(vo, -7.0f), 7.0f);
                    float sg  = 1.0f / (1.0f + expf(-1.702f * glu));
                    g_act[(size_t)row * NI + (c >> 1)] = glu * sg * (lin + 1.0f);
                }
            } else {
                float s2 = g_s2[row];
                int flat = g_row_flat[row];
#pragma unroll
                for (int na = 0; na < 4; na++) {
                    int c = n0 + wn + na * 8 + 2 * tg;
                    float o0 = (float)acc[ma][na][half * 2]     * s2 * wsc[(size_t)e * NC + c]     + wbi[(size_t)e * NC + c];
                    float o1 = (float)acc[ma][na][half * 2 + 1] * s2 * wsc[(size_t)e * NC + c + 1] + wbi[(size_t)e * NC + c + 1];
                    *(float2*)&g_dn[(size_t)flat * NH + c] = make_float2(o0, o1);
                }
            }
        }
    }
}

// ---------------- 4. requant activations ----------------
__global__ void quant_act() {
    int b = blockIdx.x;
    int e = b >> 8, m = b & 255;
    if (m >= g_count[e]) return;
    int tid = threadIdx.x;
    __shared__ float red[256];
    const float* row = &g_act[(size_t)b * NI];
    float mx = 0.f;
    for (int i = tid; i < NI; i += 256) mx = fmaxf(mx, fabsf(row[i]));
    red[tid] = mx; __syncthreads();
    for (int s = 128; s > 0; s >>= 1) { if (tid < s) red[tid] = fmaxf(red[tid], red[tid + s]); __syncthreads(); }
    float sc = red[0] / 127.0f;
    if (tid == 0) g_s2[b] = sc;
    float sd = (sc > 0.f) ? sc : 1.0f;
    for (int i = tid; i < NI; i += 256) {
        float q = rintf(row[i] / sd);
        q = fminf(fmaxf(q, -127.f), 127.f);
        g_q2[(size_t)b * NI + i] = (int8_t)q;
    }
}

// ---------------- 6. weighted gather-combine ----------------
__global__ void combine_kernel(float* __restrict__ out) {
    int t = blockIdx.x, tid = threadIdx.x;
    float w[NK]; int ps[NK];
#pragma unroll
    for (int k = 0; k < NK; k++) { w[k] = g_topk_w[t * NK + k]; ps[k] = g_pos[t * NK + k]; }
    for (int i = tid * 4; i < NH; i += 256 * 4) {
        float4 a = {0.f, 0.f, 0.f, 0.f};
#pragma unroll
        for (int k = 0; k < NK; k++) {
            if (ps[k] < NCAP) {
                float4 d = *(const float4*)&g_dn[(size_t)(t * NK + k) * NH + i];
                a.x += w[k] * d.x; a.y += w[k] * d.y;
                a.z += w[k] * d.z; a.w += w[k] * d.w;
            }
        }
        *(float4*)&out[(size_t)t * NH + i] = a;
    }
}

// ---------------- launch ----------------
extern "C" void kernel_launch(void* const* d_in, const int* in_sizes, int n_in,
                              void* d_out, int out_size) {
    int i_hs = 0, i_rl = 1, i_gu = 2, i_gus = 3, i_gub = 4, i_dn = 5, i_dns = 6, i_dnb = 7;
    if (n_in == 8) {
        int a_gu = -1, b_gu = -1, a_dn = -1, b_dn = -1;
        int hs = -1, rl = -1, gu = -1, dn = -1;
        for (int i = 0; i < n_in; i++) {
            long long s = in_sizes[i];
            if (s == (long long)NT * NH) hs = i;
            else if (s == (long long)NT * NE) rl = i;
            else if (s == (long long)NE * NH * N1) gu = i;
            else if (s == (long long)NE * NI * NH) dn = i;
            else if (s == (long long)NE * N1) { if (a_gu < 0) a_gu = i; else b_gu = i; }
            else if (s == (long long)NE * NH) { if (a_dn < 0) a_dn = i; else b_dn = i; }
        }
        if (hs >= 0 && rl >= 0 && gu >= 0 && dn >= 0 &&
            a_gu >= 0 && b_gu >= 0 && a_dn >= 0 && b_dn >= 0) {
            i_hs = hs; i_rl = rl; i_gu = gu; i_dn = dn;
            i_gus = a_gu; i_gub = b_gu; i_dns = a_dn; i_dnb = b_dn;
        }
    }

    const float* hs    = (const float*)d_in[i_hs];
    const float* rl    = (const float*)d_in[i_rl];
    const void*  gup   = d_in[i_gu];
    const float* gup_a = (const float*)d_in[i_gus];
    const float* gup_b = (const float*)d_in[i_gub];
    const void*  dnw   = d_in[i_dn];
    const float* dn_a  = (const float*)d_in[i_dns];
    const float* dn_b  = (const float*)d_in[i_dnb];
    float* out = (float*)d_out;

    cudaFuncSetAttribute(gemm_cp<N1, 1>, cudaFuncAttributeMaxDynamicSharedMemorySize, SM_TOTAL);
    cudaFuncSetAttribute(gemm_cp<NH, 2>, cudaFuncAttributeMaxDynamicSharedMemorySize, SM_TOTAL);

    prep_kernel<<<2, 256>>>(gup, gup_a, dn_a);                                       // 1
    routing_kernel<<<1, 1024>>>(rl);                                                 // 2
    quant_x<<<NT, 256>>>(hs);                                                        // 3
    gemm_cp<N1, 1><<<dim3(N1 / 128, NE * 3), 256, SM_TOTAL>>>(gup, gup_a, gup_b);    // 4 (profiled)
    quant_act<<<NE * NCAP, 256>>>();                                                 // 5
    gemm_cp<NH, 2><<<dim3(NH / 128, NE * 3), 256, SM_TOTAL>>>(dnw, dn_a, dn_b);      // 6
    combine_kernel<<<NT, 256>>>(out);                                                // 7
}

// round 17
// speedup vs baseline: 1.5275x; 1.1061x over previous
#include <cuda_runtime.h>
#include <cuda_bf16.h>
#include <cstdint>
#include <cstddef>

#define NE   32
#define NK   4
#define NH   2048
#define NI   2048
#define NT   512
#define NCAP 256
#define N1   4096   // 2*I
#define NKC  64     // K / BK, BK = 32

// dynamic smem: BM=64 BK=32; A 4-stage ring + double packed-B buffer (B staged in registers)
#define SM_A_STRIDE 3072      // 64 rows * 48B (padded, conflict-free frag reads)
#define SM_P_OFF    12288     // 4 * SM_A_STRIDE
#define SM_P_HALF   1088      // 8 * 136 ints
#define SM_TOTAL    20992     // SM_P_OFF + 2 * 4352

// ---------------- scratch ----------------
__device__ int8_t g_qx[NT * NH];
__device__ float  g_xscale[NT];
__device__ int    g_topk_ids[NT * NK];
__device__ float  g_topk_w[NT * NK];
__device__ int    g_pos[NT * NK];
__device__ int    g_count[NE];
__device__ int    g_row_tok[NE * NCAP];
__device__ int    g_row_flat[NE * NCAP];
__device__ float  g_act[(size_t)NE * NCAP * NI];
__device__ int8_t g_q2[(size_t)NE * NCAP * NI];
__device__ float  g_s2[NE * NCAP];
__device__ float  g_dn[(size_t)NT * NK * NH];

__device__ int    g_mode;      // 0=int8 packed, 1=int32, 2=f32, 3=bf16
__device__ int    g_gu_swap;
__device__ int    g_dn_swap;

// ---------------- 0. detect dtype + classify scale/bias ----------------
__global__ void prep_kernel(const void* __restrict__ w,
                            const float* __restrict__ gua, const float* __restrict__ dna) {
    if (blockIdx.x == 0) {
        __shared__ int votes[4];
        if (threadIdx.x < 4) votes[threadIdx.x] = 0;
        __syncthreads();
        const int* wi = (const int*)w;
        int v8 = 0, v32 = 0, vf = 0, vb = 0;
        for (int i = threadIdx.x; i < 8192; i += 256) {
            int v = wi[i];
            if (v == 0) continue;
            if (v >= -127 && v <= 127) { v32++; continue; }
            float f = __int_as_float(v);
            if (fabsf(f) <= 127.f && f == rintf(f)) { vf++; continue; }
            float b0 = __uint_as_float(((unsigned)v & 0xFFFFu) << 16);
            float b1 = __uint_as_float(((unsigned)v) & 0xFFFF0000u);
            if (fabsf(b0) <= 127.f && b0 == rintf(b0) &&
                fabsf(b1) <= 127.f && b1 == rintf(b1)) { vb++; continue; }
            v8++;
        }
        atomicAdd(&votes[0], v8); atomicAdd(&votes[1], v32);
        atomicAdd(&votes[2], vf); atomicAdd(&votes[3], vb);
        __syncthreads();
        if (threadIdx.x == 0) {
            int m = 0;
            for (int j = 1; j < 4; j++) if (votes[j] > votes[m]) m = j;
            g_mode = m;
        }
    } else if (threadIdx.x < 32) {
        int lane = threadIdx.x;
        float a = gua[lane], b = dna[lane];
        unsigned m1 = __ballot_sync(0xffffffffu, a > 0.f && a < 1e-2f);
        unsigned m2 = __ballot_sync(0xffffffffu, b > 0.f && b < 1e-2f);
        if (lane == 0) {
            g_gu_swap = (m1 == 0xffffffffu) ? 0 : 1;
            g_dn_swap = (m2 == 0xffffffffu) ? 0 : 1;
        }
    }
}

// ---------------- 1. routing ----------------
__global__ void routing_kernel(const float* __restrict__ logits) {
    int tid = threadIdx.x;
    if (tid < NT) {
        float v[NE];
#pragma unroll
        for (int j = 0; j < NE; j++) v[j] = logits[tid * NE + j];
        int ids[NK]; float vals[NK];
#pragma unroll
        for (int k = 0; k < NK; k++) {
            int bi = 0; float bv = v[0];
#pragma unroll
            for (int j = 1; j < NE; j++)
                if (v[j] > bv) { bv = v[j]; bi = j; }
            ids[k] = bi; vals[k] = bv; v[bi] = -3.4e38f;
        }
        float m = vals[0], s = 0.f, w[NK];
#pragma unroll
        for (int k = 0; k < NK; k++) { w[k] = expf(vals[k] - m); s += w[k]; }
#pragma unroll
        for (int k = 0; k < NK; k++) {
            g_topk_w[tid * NK + k]  = w[k] / s;
            g_topk_ids[tid * NK + k] = ids[k];
        }
    }
    __syncthreads();
    int wp = tid >> 5, lane = tid & 31;
    if (wp < NE) {
        int cnt = 0;
        for (int base = 0; base < NT * NK; base += 32) {
            int fe = g_topk_ids[base + lane];
            unsigned msk = __ballot_sync(0xffffffffu, fe == wp);
            if (fe == wp) {
                int p = cnt + __popc(msk & ((1u << lane) - 1u));
                g_pos[base + lane] = p;
                if (p < NCAP) {
                    g_row_tok[wp * NCAP + p]  = (base + lane) >> 2;
                    g_row_flat[wp * NCAP + p] = base + lane;
                }
            }
            cnt += __popc(msk);
        }
        if (lane == 0) g_count[wp] = cnt;
    }
}

// ---------------- 2. per-token dynamic int8 quant ----------------
__global__ void quant_x(const float* __restrict__ x) {
    int t = blockIdx.x, tid = threadIdx.x;
    __shared__ float red[256];
    const float* row = x + (size_t)t * NH;
    float mx = 0.f;
    for (int i = tid; i < NH; i += 256) mx = fmaxf(mx, fabsf(row[i]));
    red[tid] = mx; __syncthreads();
    for (int s = 128; s > 0; s >>= 1) { if (tid < s) red[tid] = fmaxf(red[tid], red[tid + s]); __syncthreads(); }
    float sc = red[0] / 127.0f;
    if (tid == 0) g_xscale[t] = sc;
    float sd = (sc > 0.f) ? sc : 1.0f;
    for (int i = tid; i < NH; i += 256) {
        float q = rintf(row[i] / sd);
        q = fminf(fmaxf(q, -127.f), 127.f);
        g_qx[(size_t)t * NH + i] = (int8_t)q;
    }
}

// ---------------- GEMM helpers ----------------
#define MMA_S8(d, a0, a1, a2, a3, b0, b1)                                         \
    asm volatile("mma.sync.aligned.m16n8k32.row.col.s32.s8.s8.s32 "               \
                 "{%0,%1,%2,%3}, {%4,%5,%6,%7}, {%8,%9}, {%0,%1,%2,%3};"          \
                 : "+r"(d[0]), "+r"(d[1]), "+r"(d[2]), "+r"(d[3])                 \
                 : "r"(a0), "r"(a1), "r"(a2), "r"(a3), "r"(b0), "r"(b1))

__device__ __forceinline__ void cpa16(uint32_t dst, const void* src) {
    asm volatile("cp.async.cg.shared.global [%0], [%1], 16;" :: "r"(dst), "l"(src));
}

__device__ __forceinline__ int pack_i32(int4 v) {
    int t0 = __byte_perm(v.x, v.y, 0x0040);
    int t1 = __byte_perm(v.z, v.w, 0x0040);
    return __byte_perm(t0, t1, 0x5410);
}
__device__ __forceinline__ int pack_f32(int4 v) {
    float4 f = *(float4*)&v;
    int a = __float2int_rn(f.x) & 255, b = __float2int_rn(f.y) & 255;
    int c = __float2int_rn(f.z) & 255, d = __float2int_rn(f.w);
    return a | (b << 8) | (c << 16) | (d << 24);
}
__device__ __forceinline__ int pack_bf16x4(int lo, int hi) {
    int a = __float2int_rn(__uint_as_float(((unsigned)lo & 0xFFFFu) << 16)) & 255;
    int b = __float2int_rn(__uint_as_float((unsigned)lo & 0xFFFF0000u)) & 255;
    int c = __float2int_rn(__uint_as_float(((unsigned)hi & 0xFFFFu) << 16)) & 255;
    int d = __float2int_rn(__uint_as_float((unsigned)hi & 0xFFFF0000u));
    return a | (b << 8) | (c << 16) | (d << 24);
}

// ---------------- tensor-core grouped int8 GEMM: BM=64 BN=128 BK=32 ----------------
// B staged in REGISTERS (LDG), packed in regs, STS only 16B packed -> single barrier/iter.
// A via cp.async 4-stage ring (mod 4; issue(kc+2) never collides with frags(kc-1)).
// Schedule per iter kc:  stB(kc) -> issueA(kc+2) -> waitA -> BARRIER -> ldgB(kc+1) -> frags+mma(kc)
// EPI==1: A = gathered g_qx rows, epilogue dequant+bias+swiglu -> g_act
// EPI==2: A = g_q2 rows,          epilogue dequant+bias -> g_dn[flat]
template <int NC, int EPI>
__global__ __launch_bounds__(256, 3) void gemm_cp(const void* __restrict__ W,
                                                  const float* __restrict__ sb_a,
                                                  const float* __restrict__ sb_b) {
    const int e  = blockIdx.y >> 2;            // 4 m-tiles of 64 cover CAP=256
    const int m0 = (blockIdx.y & 3) * 64;
    const int cnt = g_count[e];
    if (m0 >= cnt) return;
    const int n0 = blockIdx.x * 128;
    const int mode = g_mode;

    const int swap = (EPI == 1) ? g_gu_swap : g_dn_swap;
    const float* wsc = swap ? sb_b : sb_a;
    const float* wbi = swap ? sb_a : sb_b;

    extern __shared__ char smem[];
    const uint32_t sbase = (uint32_t)__cvta_generic_to_shared(smem);

    const int tid = threadIdx.x;
    const int lane = tid & 31, wid = tid >> 5;
    const int wm = (wid & 1) * 32, wn = (wid >> 1) * 32;   // 2m x 4n warp grid
    const int g = lane >> 2, tg = lane & 3;

    // A source: 64 rows x 2 chunks of 16B per stage -> threads 0..127
    const int aM = tid >> 1, aOff = (tid & 1) * 16;
    const int8_t* aPtr = nullptr;
    if (tid < 128) {
        int m = m0 + aM;
        bool val = m < cnt;
        if (EPI == 1) {
            int tok = val ? g_row_tok[e * NCAP + m] : 0;
            aPtr = g_qx + (size_t)tok * NH;
        } else {
            aPtr = g_q2 + (size_t)(e * NCAP + (val ? m : 0)) * NI;
        }
    }
    const size_t ebase = (size_t)e * 2048 * NC;

    auto issueA = [&](int s) {
        if (tid < 128)
            cpa16(sbase + (s & 3) * SM_A_STRIDE + aM * 48 + aOff, aPtr + s * 32 + aOff);
        asm volatile("cp.async.commit_group;");
    };

    // B register staging: thread (kq=wid, nn=lane) owns rows 4*kq..4*kq+3, cols n0+nn*4..+3
    const int kq = wid, nn = lane;
    int4 brw[4];

    auto ldgB = [&](int s) {
        if (mode == 1 || mode == 2) {
#pragma unroll
            for (int j = 0; j < 4; j++)
                brw[j] = *((const int4*)((const int*)W + ebase + (size_t)(s * 32 + 4 * kq + j) * NC + n0) + nn);
        } else if (mode == 3) {
#pragma unroll
            for (int j = 0; j < 4; j++) {
                uint2 u = *((const uint2*)((const __nv_bfloat16*)W + ebase + (size_t)(s * 32 + 4 * kq + j) * NC + n0) + nn);
                brw[j].x = (int)u.x; brw[j].y = (int)u.y;
            }
        } else {
#pragma unroll
            for (int j = 0; j < 4; j++)
                brw[j].x = *((const int*)((const int8_t*)W + ebase + (size_t)(s * 32 + 4 * kq + j) * NC + n0) + nn);
        }
    };

    auto stB = [&](int buf) {
        int r[4];
        if (mode == 0) {
#pragma unroll
            for (int j = 0; j < 4; j++) r[j] = brw[j].x;
        } else if (mode == 1) {
#pragma unroll
            for (int j = 0; j < 4; j++) r[j] = pack_i32(brw[j]);
        } else if (mode == 2) {
#pragma unroll
            for (int j = 0; j < 4; j++) r[j] = pack_f32(brw[j]);
        } else {
#pragma unroll
            for (int j = 0; j < 4; j++) r[j] = pack_bf16x4(brw[j].x, brw[j].y);
        }
        int t0 = __byte_perm(r[0], r[1], 0x5140);
        int t1 = __byte_perm(r[0], r[1], 0x7362);
        int t2 = __byte_perm(r[2], r[3], 0x5140);
        int t3 = __byte_perm(r[2], r[3], 0x7362);
        int* bp = (int*)(smem + SM_P_OFF) + buf * SM_P_HALF;
        *(int4*)&bp[kq * 136 + nn * 4] = make_int4(__byte_perm(t0, t2, 0x5410),
                                                   __byte_perm(t0, t2, 0x7632),
                                                   __byte_perm(t1, t3, 0x5410),
                                                   __byte_perm(t1, t3, 0x7632));
    };

    int acc[2][4][4];
#pragma unroll
    for (int i = 0; i < 2; i++)
#pragma unroll
        for (int j = 0; j < 4; j++)
#pragma unroll
            for (int q = 0; q < 4; q++) acc[i][j][q] = 0;

    issueA(0); issueA(1);
    ldgB(0);

    for (int kc = 0; kc < NKC; kc++) {
        // packed store of current B chunk (brw holds stage kc)
        stB(kc & 1);
        // A pipeline refill: slot (kc+2)&3; frags(kc-1) used slot (kc-1)&3 (different); WAR two barriers deep
        if (kc + 2 < NKC) issueA(kc + 2);
        // per-thread A completion for stage kc (then barrier gives cross-thread visibility)
        if (kc + 2 < NKC)      asm volatile("cp.async.wait_group 2;" ::: "memory");
        else if (kc + 1 < NKC) asm volatile("cp.async.wait_group 1;" ::: "memory");
        else                   asm volatile("cp.async.wait_group 0;" ::: "memory");
        __syncthreads();   // ONE barrier: packed[kc&1] + A stage kc visible everywhere

        // prefetch next B chunk into registers (latency covered by frags+mma)
        if (kc + 1 < NKC) ldgB(kc + 1);

        // fragments + mma
        const int* aSv = (const int*)(smem + (kc & 3) * SM_A_STRIDE);
        const int* bp  = (const int*)(smem + SM_P_OFF) + (kc & 1) * SM_P_HALF;
        int bf[4][2];
#pragma unroll
        for (int na = 0; na < 4; na++) {
            bf[na][0] = bp[tg * 136 + wn + na * 8 + g];
            bf[na][1] = bp[(tg + 4) * 136 + wn + na * 8 + g];
        }
#pragma unroll
        for (int ma = 0; ma < 2; ma++) {
            int mrow = wm + ma * 16 + g;
            int a0 = aSv[mrow * 12 + tg];
            int a1 = aSv[(mrow + 8) * 12 + tg];
            int a2 = aSv[mrow * 12 + tg + 4];
            int a3 = aSv[(mrow + 8) * 12 + tg + 4];
#pragma unroll
            for (int na = 0; na < 4; na++)
                MMA_S8(acc[ma][na], a0, a1, a2, a3, bf[na][0], bf[na][1]);
        }
    }

    // ---- epilogue ----
#pragma unroll
    for (int ma = 0; ma < 2; ma++) {
        int rbase = m0 + wm + ma * 16 + g;
#pragma unroll
        for (int half = 0; half < 2; half++) {
            int r = rbase + half * 8;
            if (r >= cnt) continue;
            int row = e * NCAP + r;
            if (EPI == 1) {
                float xs = g_xscale[g_row_tok[row]];
#pragma unroll
                for (int na = 0; na < 4; na++) {
                    int c = n0 + wn + na * 8 + 2 * tg;
                    float ve = (float)acc[ma][na][half * 2]     * xs * wsc[(size_t)e * NC + c]     + wbi[(size_t)e * NC + c];
                    float vo = (float)acc[ma][na][half * 2 + 1] * xs * wsc[(size_t)e * NC + c + 1] + wbi[(size_t)e * NC + c + 1];
                    float glu = fminf(ve, 7.0f);
                    float lin = fminf(fmaxf(vo, -7.0f), 7.0f);
                    float sg  = 1.0f / (1.0f + expf(-1.702f * glu));
                    g_act[(size_t)row * NI + (c >> 1)] = glu * sg * (lin + 1.0f);
                }
            } else {
                float s2 = g_s2[row];
                int flat = g_row_flat[row];
#pragma unroll
                for (int na = 0; na < 4; na++) {
                    int c = n0 + wn + na * 8 + 2 * tg;
                    float o0 = (float)acc[ma][na][half * 2]     * s2 * wsc[(size_t)e * NC + c]     + wbi[(size_t)e * NC + c];
                    float o1 = (float)acc[ma][na][half * 2 + 1] * s2 * wsc[(size_t)e * NC + c + 1] + wbi[(size_t)e * NC + c + 1];
                    *(float2*)&g_dn[(size_t)flat * NH + c] = make_float2(o0, o1);
                }
            }
        }
    }
}

// ---------------- 4. requant activations ----------------
__global__ void quant_act() {
    int b = blockIdx.x;
    int e = b >> 8, m = b & 255;
    if (m >= g_count[e]) return;
    int tid = threadIdx.x;
    __shared__ float red[256];
    const float* row = &g_act[(size_t)b * NI];
    float mx = 0.f;
    for (int i = tid; i < NI; i += 256) mx = fmaxf(mx, fabsf(row[i]));
    red[tid] = mx; __syncthreads();
    for (int s = 128; s > 0; s >>= 1) { if (tid < s) red[tid] = fmaxf(red[tid], red[tid + s]); __syncthreads(); }
    float sc = red[0] / 127.0f;
    if (tid == 0) g_s2[b] = sc;
    float sd = (sc > 0.f) ? sc : 1.0f;
    for (int i = tid; i < NI; i += 256) {
        float q = rintf(row[i] / sd);
        q = fminf(fmaxf(q, -127.f), 127.f);
        g_q2[(size_t)b * NI + i] = (int8_t)q;
    }
}

// ---------------- 6. weighted gather-combine ----------------
__global__ void combine_kernel(float* __restrict__ out) {
    int t = blockIdx.x, tid = threadIdx.x;
    float w[NK]; int ps[NK];
#pragma unroll
    for (int k = 0; k < NK; k++) { w[k] = g_topk_w[t * NK + k]; ps[k] = g_pos[t * NK + k]; }
    for (int i = tid * 4; i < NH; i += 256 * 4) {
        float4 a = {0.f, 0.f, 0.f, 0.f};
#pragma unroll
        for (int k = 0; k < NK; k++) {
            if (ps[k] < NCAP) {
                float4 d = *(const float4*)&g_dn[(size_t)(t * NK + k) * NH + i];
                a.x += w[k] * d.x; a.y += w[k] * d.y;
                a.z += w[k] * d.z; a.w += w[k] * d.w;
            }
        }
        *(float4*)&out[(size_t)t * NH + i] = a;
    }
}

// ---------------- launch ----------------
extern "C" void kernel_launch(void* const* d_in, const int* in_sizes, int n_in,
                              void* d_out, int out_size) {
    int i_hs = 0, i_rl = 1, i_gu = 2, i_gus = 3, i_gub = 4, i_dn = 5, i_dns = 6, i_dnb = 7;
    if (n_in == 8) {
        int a_gu = -1, b_gu = -1, a_dn = -1, b_dn = -1;
        int hs = -1, rl = -1, gu = -1, dn = -1;
        for (int i = 0; i < n_in; i++) {
            long long s = in_sizes[i];
            if (s == (long long)NT * NH) hs = i;
            else if (s == (long long)NT * NE) rl = i;
            else if (s == (long long)NE * NH * N1) gu = i;
            else if (s == (long long)NE * NI * NH) dn = i;
            else if (s == (long long)NE * N1) { if (a_gu < 0) a_gu = i; else b_gu = i; }
            else if (s == (long long)NE * NH) { if (a_dn < 0) a_dn = i; else b_dn = i; }
        }
        if (hs >= 0 && rl >= 0 && gu >= 0 && dn >= 0 &&
            a_gu >= 0 && b_gu >= 0 && a_dn >= 0 && b_dn >= 0) {
            i_hs = hs; i_rl = rl; i_gu = gu; i_dn = dn;
            i_gus = a_gu; i_gub = b_gu; i_dns = a_dn; i_dnb = b_dn;
        }
    }

    const float* hs    = (const float*)d_in[i_hs];
    const float* rl    = (const float*)d_in[i_rl];
    const void*  gup   = d_in[i_gu];
    const float* gup_a = (const float*)d_in[i_gus];
    const float* gup_b = (const float*)d_in[i_gub];
    const void*  dnw   = d_in[i_dn];
    const float* dn_a  = (const float*)d_in[i_dns];
    const float* dn_b  = (const float*)d_in[i_dnb];
    float* out = (float*)d_out;

    cudaFuncSetAttribute(gemm_cp<N1, 1>, cudaFuncAttributeMaxDynamicSharedMemorySize, SM_TOTAL);
    cudaFuncSetAttribute(gemm_cp<NH, 2>, cudaFuncAttributeMaxDynamicSharedMemorySize, SM_TOTAL);

    prep_kernel<<<2, 256>>>(gup, gup_a, dn_a);                                       // 1
    routing_kernel<<<1, 1024>>>(rl);                                                 // 2
    quant_x<<<NT, 256>>>(hs);                                                        // 3
    gemm_cp<N1, 1><<<dim3(N1 / 128, NE * 4), 256, SM_TOTAL>>>(gup, gup_a, gup_b);    // 4 (profiled)
    quant_act<<<NE * NCAP, 256>>>();                                                 // 5
    gemm_cp<NH, 2><<<dim3(NH / 128, NE * 4), 256, SM_TOTAL>>>(dnw, dn_a, dn_b);      // 6
    combine_kernel<<<NT, 256>>>(out);                                                // 7
}